// round 1
// baseline (speedup 1.0000x reference)
#include <cuda_runtime.h>
#include <math.h>

#define MAXN 100000
#define MAXE 1600000

// ---------------- static device scratch (no allocs allowed) ----------------
__device__ float g_t[(size_t)MAXN * 128];   // transformed features (stride = layer dim)
__device__ float g_y[(size_t)MAXN * 128];   // aggregated features
__device__ float g_t3[(size_t)MAXN * 2];    // layer-3 transformed
__device__ float g_y3[(size_t)MAXN * 2];    // layer-3 aggregated
__device__ float g_rs_s[MAXN];              // rsqrt(max(out-degree,1))
__device__ float g_rs_r[MAXN];              // rsqrt(max(in-degree,1))
__device__ int   g_deg_s[MAXN];
__device__ int   g_deg_r[MAXN];
__device__ int   g_off[MAXN];               // CSR row offsets (by receiver)
__device__ int   g_cur[MAXN];               // scatter cursors
__device__ int   g_srt[MAXE];               // senders sorted by receiver
__device__ int   g_bsum[128];
__device__ int   g_boff[128];

// ---------------- setup kernels ----------------
__global__ void k_zero(float* out, int out_n, int N) {
    int i = blockIdx.x * blockDim.x + threadIdx.x;
    if (i < N) { g_deg_s[i] = 0; g_deg_r[i] = 0; }
    if (i < out_n) out[i] = 0.f;
}

__global__ void k_deg(const int* __restrict__ snd, const int* __restrict__ rcv, int E) {
    int stride = gridDim.x * blockDim.x;
    for (int e = blockIdx.x * blockDim.x + threadIdx.x; e < E; e += stride) {
        atomicAdd(&g_deg_s[snd[e]], 1);
        atomicAdd(&g_deg_r[rcv[e]], 1);
    }
}

// block-wide exclusive scan of g_deg_r (1024 elems/block) -> g_off (partial), g_bsum
__global__ void k_scan1(int N) {
    __shared__ int wsum[32];
    int i = blockIdx.x * 1024 + threadIdx.x;
    int v = (i < N) ? g_deg_r[i] : 0;
    int lane = threadIdx.x & 31, wid = threadIdx.x >> 5;
    int incl = v;
#pragma unroll
    for (int d = 1; d < 32; d <<= 1) {
        int t = __shfl_up_sync(0xffffffffu, incl, d);
        if (lane >= d) incl += t;
    }
    if (lane == 31) wsum[wid] = incl;
    __syncthreads();
    if (wid == 0) {
        int wv = wsum[lane];
#pragma unroll
        for (int d = 1; d < 32; d <<= 1) {
            int t = __shfl_up_sync(0xffffffffu, wv, d);
            if (lane >= d) wv += t;
        }
        wsum[lane] = wv;
    }
    __syncthreads();
    int wexcl = wid ? wsum[wid - 1] : 0;
    if (i < N) g_off[i] = wexcl + incl - v;
    if (threadIdx.x == 1023) g_bsum[blockIdx.x] = wsum[31];
}

__global__ void k_scan2(int nb) {
    int run = 0;
    for (int b = 0; b < nb; b++) { g_boff[b] = run; run += g_bsum[b]; }
}

// finalize offsets + cursors + normalization factors
__global__ void k_scan3(int N) {
    int i = blockIdx.x * blockDim.x + threadIdx.x;
    if (i >= N) return;
    int o = g_off[i] + g_boff[i >> 10];
    g_off[i] = o;
    g_cur[i] = o;
    g_rs_s[i] = rsqrtf(fmaxf((float)g_deg_s[i], 1.f));
    g_rs_r[i] = rsqrtf(fmaxf((float)g_deg_r[i], 1.f));
}

__global__ void k_scatter(const int* __restrict__ snd, const int* __restrict__ rcv, int E) {
    int stride = gridDim.x * blockDim.x;
    for (int e = blockIdx.x * blockDim.x + threadIdx.x; e < E; e += stride) {
        int p = atomicAdd(&g_cur[rcv[e]], 1);
        g_srt[p] = snd[e];
    }
}

// ---------------- layer 1 transform: x[N,9] @ W1[9,64] + b1, * rs_s ----------------
__global__ void k_l1(const float* __restrict__ x, const float* __restrict__ W1,
                     const float* __restrict__ b1, int N) {
    __shared__ float sW[9 * 64];
    __shared__ float sb[64];
    int tid = threadIdx.x;
    for (int i = tid; i < 576; i += blockDim.x) sW[i] = W1[i];
    if (tid < 64) sb[tid] = b1[tid];
    __syncthreads();
    int node = blockIdx.x * 4 + (tid >> 6);
    int j = tid & 63;
    if (node >= N) return;
    const float* xr = x + node * 9;
    float acc = sb[j];
#pragma unroll
    for (int k = 0; k < 9; k++) acc += __ldg(xr + k) * sW[k * 64 + j];
    g_t[(size_t)node * 64 + j] = acc * g_rs_s[node];
}

// ---------------- aggregation: warp per node ----------------
__global__ void k_agg64(int N) {
    int w = (blockIdx.x * blockDim.x + threadIdx.x) >> 5;
    if (w >= N) return;
    int lane = threadIdx.x & 31;
    int beg = g_off[w], cnt = g_deg_r[w];
    float ax = 0.f, ay = 0.f;
    const int* sp = g_srt + beg;
#pragma unroll 4
    for (int e = 0; e < cnt; e++) {
        int s = __ldg(sp + e);
        float2 v = *(const float2*)(g_t + (size_t)s * 64 + lane * 2);
        ax += v.x; ay += v.y;
    }
    float rr = g_rs_r[w];
    *(float2*)(g_y + (size_t)w * 64 + lane * 2) = make_float2(ax * rr, ay * rr);
}

__global__ void k_agg128(int N) {
    int w = (blockIdx.x * blockDim.x + threadIdx.x) >> 5;
    if (w >= N) return;
    int lane = threadIdx.x & 31;
    int beg = g_off[w], cnt = g_deg_r[w];
    float ax = 0.f, ay = 0.f, az = 0.f, aw = 0.f;
    const int* sp = g_srt + beg;
#pragma unroll 4
    for (int e = 0; e < cnt; e++) {
        int s = __ldg(sp + e);
        float4 v = *(const float4*)(g_t + (size_t)s * 128 + lane * 4);
        ax += v.x; ay += v.y; az += v.z; aw += v.w;
    }
    float rr = g_rs_r[w];
    *(float4*)(g_y + (size_t)w * 128 + lane * 4) =
        make_float4(ax * rr, ay * rr, az * rr, aw * rr);
}

// ---------------- layer 2 transform: relu(y1)[64] @ W2[64,128] + b2, * rs_s --------
__global__ void __launch_bounds__(128) k_l2(const float* __restrict__ W2,
                                            const float* __restrict__ b2, int N) {
    int j = threadIdx.x;  // 0..127 = output column
    float w[64];
#pragma unroll
    for (int k = 0; k < 64; k++) w[k] = W2[k * 128 + j];
    float bj = b2[j];
    __shared__ float sin[64 * 4];
    int base = blockIdx.x * 64;  // 64 nodes per block
    for (int t0 = 0; t0 < 64; t0 += 4) {
        int nidx = base + t0;
        __syncthreads();
        for (int i = j; i < 256; i += 128) {
            int nn = nidx + (i >> 6);
            sin[i] = (nn < N) ? fmaxf(g_y[(size_t)nn * 64 + (i & 63)], 0.f) : 0.f;
        }
        __syncthreads();
#pragma unroll
        for (int q = 0; q < 4; q++) {
            int node = nidx + q;
            if (node >= N) break;
            float acc = bj;
#pragma unroll
            for (int k = 0; k < 64; k++) acc += sin[q * 64 + k] * w[k];
            g_t[(size_t)node * 128 + j] = acc * g_rs_s[node];
        }
    }
}

// ---------------- layer 3 transform: relu(y2)[128] @ W3[128,2] + b3, * rs_s --------
__global__ void k_l3(const float* __restrict__ W3, const float* __restrict__ b3, int N) {
    int w = (blockIdx.x * blockDim.x + threadIdx.x) >> 5;
    if (w >= N) return;
    int lane = threadIdx.x & 31;
    float4 h = *(const float4*)(g_y + (size_t)w * 128 + lane * 4);
    h.x = fmaxf(h.x, 0.f); h.y = fmaxf(h.y, 0.f);
    h.z = fmaxf(h.z, 0.f); h.w = fmaxf(h.w, 0.f);
    int k = lane * 4;
    float p0 = h.x * __ldg(W3 + k * 2)     + h.y * __ldg(W3 + k * 2 + 2)
             + h.z * __ldg(W3 + k * 2 + 4) + h.w * __ldg(W3 + k * 2 + 6);
    float p1 = h.x * __ldg(W3 + k * 2 + 1) + h.y * __ldg(W3 + k * 2 + 3)
             + h.z * __ldg(W3 + k * 2 + 5) + h.w * __ldg(W3 + k * 2 + 7);
#pragma unroll
    for (int d = 16; d; d >>= 1) {
        p0 += __shfl_down_sync(0xffffffffu, p0, d);
        p1 += __shfl_down_sync(0xffffffffu, p1, d);
    }
    if (lane == 0) {
        float rs = g_rs_s[w];
        g_t3[2 * w]     = (p0 + __ldg(b3))     * rs;
        g_t3[2 * w + 1] = (p1 + __ldg(b3 + 1)) * rs;
    }
}

__global__ void k_agg2(int N) {
    int n = blockIdx.x * blockDim.x + threadIdx.x;
    if (n >= N) return;
    int beg = g_off[n], cnt = g_deg_r[n];
    float a0 = 0.f, a1 = 0.f;
    const int* sp = g_srt + beg;
#pragma unroll 4
    for (int e = 0; e < cnt; e++) {
        int s = __ldg(sp + e);
        float2 v = *(const float2*)(g_t3 + 2 * (size_t)s);
        a0 += v.x; a1 += v.y;
    }
    float rr = g_rs_r[n];
    g_y3[2 * n]     = a0 * rr;
    g_y3[2 * n + 1] = a1 * rr;
}

__global__ void k_pool(const int* __restrict__ batch, float* __restrict__ out, int N) {
    int n = blockIdx.x * blockDim.x + threadIdx.x;
    if (n >= N) return;
    int g = batch[n];
    atomicAdd(&out[2 * g],     g_y3[2 * n]);
    atomicAdd(&out[2 * g + 1], g_y3[2 * n + 1]);
}

// ---------------- launch ----------------
extern "C" void kernel_launch(void* const* d_in, const int* in_sizes, int n_in,
                              void* d_out, int out_size) {
    const float* x   = (const float*)d_in[0];
    const int* snd   = (const int*)d_in[1];
    const int* rcv   = (const int*)d_in[2];
    const int* batch = (const int*)d_in[3];
    int N = in_sizes[0] / 9;
    int E = in_sizes[1];

    // find W1 (9*64 = 576 elements); tolerates a scalar num_graphs input in between
    int bi = 4;
    while (bi < n_in && in_sizes[bi] != 9 * 64) bi++;
    const float* W1 = (const float*)d_in[bi];
    const float* b1 = (const float*)d_in[bi + 1];
    const float* W2 = (const float*)d_in[bi + 2];
    const float* b2 = (const float*)d_in[bi + 3];
    const float* W3 = (const float*)d_in[bi + 4];
    const float* b3 = (const float*)d_in[bi + 5];
    float* out = (float*)d_out;

    int nb1024 = (N + 1023) / 1024;
    int nbN    = (N + 255) / 256;

    k_zero<<<nbN, 256>>>(out, out_size, N);
    k_deg<<<2048, 256>>>(snd, rcv, E);
    k_scan1<<<nb1024, 1024>>>(N);
    k_scan2<<<1, 1>>>(nb1024);
    k_scan3<<<nbN, 256>>>(N);
    k_scatter<<<2048, 256>>>(snd, rcv, E);

    // layer 1 (9 -> 64)
    k_l1<<<(N + 3) / 4, 256>>>(x, W1, b1, N);
    k_agg64<<<(N * 32 + 255) / 256, 256>>>(N);

    // layer 2 (64 -> 128)
    k_l2<<<(N + 63) / 64, 128>>>(W2, b2, N);
    k_agg128<<<(N * 32 + 255) / 256, 256>>>(N);

    // layer 3 (128 -> 2) + pooling
    k_l3<<<(N * 32 + 255) / 256, 256>>>(W3, b3, N);
    k_agg2<<<nbN, 256>>>(N);
    k_pool<<<nbN, 256>>>(batch, out, N);
}

// round 2
// speedup vs baseline: 1.0898x; 1.0898x over previous
#include <cuda_runtime.h>
#include <cuda_fp16.h>
#include <math.h>

#define MAXN 100000
#define MAXE 1600000

// ---------------- static device scratch (no allocs allowed) ----------------
__device__ __half g_t16[(size_t)MAXN * 128]; // transformed features, fp16 (stride = layer dim)
__device__ float  g_y[(size_t)MAXN * 128];   // aggregated features, fp32
__device__ float  g_t3[(size_t)MAXN * 2];    // layer-3 transformed
__device__ float  g_rs_s[MAXN];              // rsqrt(max(out-degree,1))
__device__ float  g_rs_r[MAXN];              // rsqrt(max(in-degree,1))
__device__ int    g_deg_s[MAXN];
__device__ int    g_deg_r[MAXN];
__device__ int    g_off[MAXN];               // CSR row offsets (by receiver)
__device__ int    g_cur[MAXN];               // scatter cursors
__device__ int    g_srt[MAXE];               // senders sorted by receiver
__device__ int    g_bsum[128];
__device__ int    g_boff[128];

// ---------------- setup kernels ----------------
__global__ void k_zero(float* out, int out_n, int N) {
    int i = blockIdx.x * blockDim.x + threadIdx.x;
    if (i < N) { g_deg_s[i] = 0; g_deg_r[i] = 0; }
    if (i < out_n) out[i] = 0.f;
}

__global__ void k_deg(const int* __restrict__ snd, const int* __restrict__ rcv, int E) {
    int stride = gridDim.x * blockDim.x;
    for (int e = blockIdx.x * blockDim.x + threadIdx.x; e < E; e += stride) {
        atomicAdd(&g_deg_s[snd[e]], 1);
        atomicAdd(&g_deg_r[rcv[e]], 1);
    }
}

// block-wide exclusive scan of g_deg_r (1024 elems/block) -> g_off (partial), g_bsum
__global__ void k_scan1(int N) {
    __shared__ int wsum[32];
    int i = blockIdx.x * 1024 + threadIdx.x;
    int v = (i < N) ? g_deg_r[i] : 0;
    int lane = threadIdx.x & 31, wid = threadIdx.x >> 5;
    int incl = v;
#pragma unroll
    for (int d = 1; d < 32; d <<= 1) {
        int t = __shfl_up_sync(0xffffffffu, incl, d);
        if (lane >= d) incl += t;
    }
    if (lane == 31) wsum[wid] = incl;
    __syncthreads();
    if (wid == 0) {
        int wv = wsum[lane];
#pragma unroll
        for (int d = 1; d < 32; d <<= 1) {
            int t = __shfl_up_sync(0xffffffffu, wv, d);
            if (lane >= d) wv += t;
        }
        wsum[lane] = wv;
    }
    __syncthreads();
    int wexcl = wid ? wsum[wid - 1] : 0;
    if (i < N) g_off[i] = wexcl + incl - v;
    if (threadIdx.x == 1023) g_bsum[blockIdx.x] = wsum[31];
}

// parallel exclusive scan of up to 128 block sums (one 128-thread block)
__global__ void k_scan2(int nb) {
    __shared__ int wsum[4];
    int tid = threadIdx.x;
    int v = (tid < nb) ? g_bsum[tid] : 0;
    int lane = tid & 31, wid = tid >> 5;
    int incl = v;
#pragma unroll
    for (int d = 1; d < 32; d <<= 1) {
        int t = __shfl_up_sync(0xffffffffu, incl, d);
        if (lane >= d) incl += t;
    }
    if (lane == 31) wsum[wid] = incl;
    __syncthreads();
    int wexcl = 0;
    for (int q = 0; q < wid; q++) wexcl += wsum[q];
    if (tid < nb) g_boff[tid] = wexcl + incl - v;
}

// finalize offsets + cursors + normalization factors
__global__ void k_scan3(int N) {
    int i = blockIdx.x * blockDim.x + threadIdx.x;
    if (i >= N) return;
    int o = g_off[i] + g_boff[i >> 10];
    g_off[i] = o;
    g_cur[i] = o;
    g_rs_s[i] = rsqrtf(fmaxf((float)g_deg_s[i], 1.f));
    g_rs_r[i] = rsqrtf(fmaxf((float)g_deg_r[i], 1.f));
}

__global__ void k_scatter(const int* __restrict__ snd, const int* __restrict__ rcv, int E) {
    int stride = gridDim.x * blockDim.x;
    for (int e = blockIdx.x * blockDim.x + threadIdx.x; e < E; e += stride) {
        int p = atomicAdd(&g_cur[rcv[e]], 1);
        g_srt[p] = snd[e];
    }
}

// ---------------- layer 1 transform: x[N,9] @ W1[9,64] + b1, * rs_s -> fp16 --------
__global__ void k_l1(const float* __restrict__ x, const float* __restrict__ W1,
                     const float* __restrict__ b1, int N) {
    __shared__ float sW[9 * 64];
    __shared__ float sb[64];
    int tid = threadIdx.x;
    for (int i = tid; i < 576; i += blockDim.x) sW[i] = W1[i];
    if (tid < 64) sb[tid] = b1[tid];
    __syncthreads();
    int node = blockIdx.x * 4 + (tid >> 6);
    int j = tid & 63;
    if (node >= N) return;
    const float* xr = x + node * 9;
    float acc = sb[j];
#pragma unroll
    for (int k = 0; k < 9; k++) acc += __ldg(xr + k) * sW[k * 64 + j];
    g_t16[(size_t)node * 64 + j] = __float2half_rn(acc * g_rs_s[node]);
}

// ---------------- aggregation: warp per node, fp16 gathers, fp32 accumulate --------
__global__ void k_agg64(int N) {
    int w = (blockIdx.x * blockDim.x + threadIdx.x) >> 5;
    if (w >= N) return;
    int lane = threadIdx.x & 31;
    int beg = g_off[w], cnt = g_deg_r[w];
    float ax = 0.f, ay = 0.f;
    const int* sp = g_srt + beg;
#pragma unroll 4
    for (int e = 0; e < cnt; e++) {
        int s = __ldg(sp + e);
        __half2 v = *(const __half2*)(g_t16 + (size_t)s * 64 + lane * 2);
        float2 f = __half22float2(v);
        ax += f.x; ay += f.y;
    }
    float rr = g_rs_r[w];
    *(float2*)(g_y + (size_t)w * 64 + lane * 2) = make_float2(ax * rr, ay * rr);
}

__global__ void k_agg128(int N) {
    int w = (blockIdx.x * blockDim.x + threadIdx.x) >> 5;
    if (w >= N) return;
    int lane = threadIdx.x & 31;
    int beg = g_off[w], cnt = g_deg_r[w];
    float ax = 0.f, ay = 0.f, az = 0.f, aw = 0.f;
    const int* sp = g_srt + beg;
#pragma unroll 4
    for (int e = 0; e < cnt; e++) {
        int s = __ldg(sp + e);
        uint2 raw = *(const uint2*)(g_t16 + (size_t)s * 128 + lane * 4);
        float2 f0 = __half22float2(*(const __half2*)&raw.x);
        float2 f1 = __half22float2(*(const __half2*)&raw.y);
        ax += f0.x; ay += f0.y; az += f1.x; aw += f1.y;
    }
    float rr = g_rs_r[w];
    *(float4*)(g_y + (size_t)w * 128 + lane * 4) =
        make_float4(ax * rr, ay * rr, az * rr, aw * rr);
}

// ---------------- layer 2 transform: relu(y1)[64] @ W2[64,128] + b2, * rs_s -> fp16
__global__ void __launch_bounds__(128) k_l2(const float* __restrict__ W2,
                                            const float* __restrict__ b2, int N) {
    int j = threadIdx.x;  // 0..127 = output column
    float w[64];
#pragma unroll
    for (int k = 0; k < 64; k++) w[k] = W2[k * 128 + j];
    float bj = b2[j];
    __shared__ float sin[64 * 4];
    int base = blockIdx.x * 64;  // 64 nodes per block
    for (int t0 = 0; t0 < 64; t0 += 4) {
        int nidx = base + t0;
        __syncthreads();
        for (int i = j; i < 256; i += 128) {
            int nn = nidx + (i >> 6);
            sin[i] = (nn < N) ? fmaxf(g_y[(size_t)nn * 64 + (i & 63)], 0.f) : 0.f;
        }
        __syncthreads();
#pragma unroll
        for (int q = 0; q < 4; q++) {
            int node = nidx + q;
            if (node >= N) break;
            float acc = bj;
#pragma unroll
            for (int k = 0; k < 64; k++) acc += sin[q * 64 + k] * w[k];
            g_t16[(size_t)node * 128 + j] = __float2half_rn(acc * g_rs_s[node]);
        }
    }
}

// ---------------- layer 3 transform: relu(y2)[128] @ W3[128,2] + b3, * rs_s --------
__global__ void k_l3(const float* __restrict__ W3, const float* __restrict__ b3, int N) {
    int w = (blockIdx.x * blockDim.x + threadIdx.x) >> 5;
    if (w >= N) return;
    int lane = threadIdx.x & 31;
    float4 h = *(const float4*)(g_y + (size_t)w * 128 + lane * 4);
    h.x = fmaxf(h.x, 0.f); h.y = fmaxf(h.y, 0.f);
    h.z = fmaxf(h.z, 0.f); h.w = fmaxf(h.w, 0.f);
    int k = lane * 4;
    float p0 = h.x * __ldg(W3 + k * 2)     + h.y * __ldg(W3 + k * 2 + 2)
             + h.z * __ldg(W3 + k * 2 + 4) + h.w * __ldg(W3 + k * 2 + 6);
    float p1 = h.x * __ldg(W3 + k * 2 + 1) + h.y * __ldg(W3 + k * 2 + 3)
             + h.z * __ldg(W3 + k * 2 + 5) + h.w * __ldg(W3 + k * 2 + 7);
#pragma unroll
    for (int d = 16; d; d >>= 1) {
        p0 += __shfl_down_sync(0xffffffffu, p0, d);
        p1 += __shfl_down_sync(0xffffffffu, p1, d);
    }
    if (lane == 0) {
        float rs = g_rs_s[w];
        g_t3[2 * w]     = (p0 + __ldg(b3))     * rs;
        g_t3[2 * w + 1] = (p1 + __ldg(b3 + 1)) * rs;
    }
}

// ---------------- fused final aggregation + graph pooling ----------------
__global__ void k_agg2pool(const int* __restrict__ batch, float* __restrict__ out, int N) {
    int n = blockIdx.x * blockDim.x + threadIdx.x;
    if (n >= N) return;
    int beg = g_off[n], cnt = g_deg_r[n];
    float a0 = 0.f, a1 = 0.f;
    const int* sp = g_srt + beg;
#pragma unroll 4
    for (int e = 0; e < cnt; e++) {
        int s = __ldg(sp + e);
        float2 v = *(const float2*)(g_t3 + 2 * (size_t)s);
        a0 += v.x; a1 += v.y;
    }
    float rr = g_rs_r[n];
    int g = batch[n];
    atomicAdd(&out[2 * g],     a0 * rr);
    atomicAdd(&out[2 * g + 1], a1 * rr);
}

// ---------------- launch ----------------
extern "C" void kernel_launch(void* const* d_in, const int* in_sizes, int n_in,
                              void* d_out, int out_size) {
    const float* x   = (const float*)d_in[0];
    const int* snd   = (const int*)d_in[1];
    const int* rcv   = (const int*)d_in[2];
    const int* batch = (const int*)d_in[3];
    int N = in_sizes[0] / 9;
    int E = in_sizes[1];

    // find W1 (9*64 = 576 elements); tolerates a scalar num_graphs input in between
    int bi = 4;
    while (bi < n_in && in_sizes[bi] != 9 * 64) bi++;
    const float* W1 = (const float*)d_in[bi];
    const float* b1 = (const float*)d_in[bi + 1];
    const float* W2 = (const float*)d_in[bi + 2];
    const float* b2 = (const float*)d_in[bi + 3];
    const float* W3 = (const float*)d_in[bi + 4];
    const float* b3 = (const float*)d_in[bi + 5];
    float* out = (float*)d_out;

    int nb1024 = (N + 1023) / 1024;
    int nbN    = (N + 255) / 256;

    k_zero<<<nbN, 256>>>(out, out_size, N);
    k_deg<<<2048, 256>>>(snd, rcv, E);
    k_scan1<<<nb1024, 1024>>>(N);
    k_scan2<<<1, 128>>>(nb1024);
    k_scan3<<<nbN, 256>>>(N);
    k_scatter<<<2048, 256>>>(snd, rcv, E);

    // layer 1 (9 -> 64)
    k_l1<<<(N + 3) / 4, 256>>>(x, W1, b1, N);
    k_agg64<<<(N * 32 + 255) / 256, 256>>>(N);

    // layer 2 (64 -> 128)
    k_l2<<<(N + 63) / 64, 128>>>(W2, b2, N);
    k_agg128<<<(N * 32 + 255) / 256, 256>>>(N);

    // layer 3 (128 -> 2) + fused aggregation/pooling
    k_l3<<<(N * 32 + 255) / 256, 256>>>(W3, b3, N);
    k_agg2pool<<<nbN, 256>>>(batch, out, N);
}